// round 14
// baseline (speedup 1.0000x reference)
#include <cuda_runtime.h>
#include <cuda_bf16.h>
#include <stdint.h>

// Problem constants (fixed by the dataset)
#define NN 50000
#define NE 800000
#define NG 256
// dims: emb 3 -> 64 -> 1024 -> 256 -> (1024, 7)

// ---------------- static scratch (no allocation allowed) ----------------
__device__ float    g_h[NN * 3];
__device__ float    g_aggr1[NN * 3];
__device__ float    g_h1[NN * 64];
__device__ uint32_t g_h1T[NN * 64];            // tf32 image of h1
__device__ uint32_t g_aggr2T[NN * 64];         // tf32 image of aggr(h1)
__device__ uint32_t g_origT[(size_t)NN * 1024];// tf32 image of original
__device__ float    g_enc[(size_t)NN * 512];   // fused [Yrel | lpre] (f32)
__device__ float    g_latent[NN * 256];
__device__ uint32_t g_latentT[NN * 256];       // tf32 image of latent
__device__ uint32_t g_aggrLT[NN * 256];        // tf32 image of aggr(latent)
__device__ uint32_t g_Wt2[1024 * 128];         // [n][k] tf32: k<64 rel | k>=64 root
__device__ uint32_t g_WtE[512 * 1024];         // [n][k] tf32: n<256 rel | n>=256 root
__device__ uint32_t g_WtD[1024 * 512];         // [n][k] tf32: k<256 rel | k>=256 root
__device__ float    g_bcat[512];               // [0 | be]
__device__ float    g_pooled[NG * 256];
__device__ float    g_counts[NG];
__device__ int      g_gstart[NG + 1];
__device__ int      g_deg[NN];
__device__ int      g_rowstart[NN + 1];
__device__ int      g_cursor[NN];
__device__ int      g_csrc[NE];

__device__ __forceinline__ float lrelu(float v) { return v >= 0.f ? v : 0.01f * v; }

__device__ __forceinline__ uint32_t f2tf32(float f) {
    uint32_t r;
    asm("cvt.rna.tf32.f32 %0, %1;" : "=r"(r) : "f"(f));
    return r;
}

__device__ __forceinline__ void mma_tf32(float c[4], const uint32_t a[4], const uint32_t b[2]) {
    asm volatile(
        "mma.sync.aligned.m16n8k8.row.col.f32.tf32.tf32.f32 "
        "{%0,%1,%2,%3}, {%4,%5,%6,%7}, {%8,%9}, {%0,%1,%2,%3};"
        : "+f"(c[0]), "+f"(c[1]), "+f"(c[2]), "+f"(c[3])
        : "r"(a[0]), "r"(a[1]), "r"(a[2]), "r"(a[3]), "r"(b[0]), "r"(b[1]));
}

__device__ __forceinline__ uint32_t smem_u32(const void* p) {
    return (uint32_t)__cvta_generic_to_shared(p);
}
__device__ __forceinline__ void cp_async16(uint32_t dst, const void* src, int src_bytes) {
    asm volatile("cp.async.cg.shared.global [%0], [%1], 16, %2;"
                 :: "r"(dst), "l"(src), "r"(src_bytes));
}
__device__ __forceinline__ void cp_commit() {
    asm volatile("cp.async.commit_group;");
}
__device__ __forceinline__ void cp_wait2() {
    asm volatile("cp.async.wait_group 2;");
}

// ---------------- tiny utility kernels ----------------
__global__ void k_zero_int(int* p, int n) {
    int i = blockIdx.x * blockDim.x + threadIdx.x;
    if (i < n) p[i] = 0;
}

// histogram of dst
__global__ void k_hist(const int* __restrict__ ei) {
    int e = blockIdx.x * blockDim.x + threadIdx.x;
    if (e < NE) atomicAdd(&g_deg[ei[NE + e]], 1);
}

// single-block exclusive scan over g_deg -> g_rowstart, g_cursor
__global__ void k_scan() {
    __shared__ int warp_sums[32];
    int lane = threadIdx.x & 31, wid = threadIdx.x >> 5;
    int carry = 0;
    for (int base = 0; base < NN; base += 1024) {
        int i = base + threadIdx.x;
        int v = (i < NN) ? g_deg[i] : 0;
        int incl = v;
        #pragma unroll
        for (int d = 1; d < 32; d <<= 1) {
            int t = __shfl_up_sync(0xFFFFFFFFu, incl, d);
            if (lane >= d) incl += t;
        }
        if (lane == 31) warp_sums[wid] = incl;
        __syncthreads();
        if (wid == 0) {
            int s = warp_sums[lane];
            #pragma unroll
            for (int d = 1; d < 32; d <<= 1) {
                int t = __shfl_up_sync(0xFFFFFFFFu, s, d);
                if (lane >= d) s += t;
            }
            warp_sums[lane] = s;
        }
        __syncthreads();
        int excl_warp = (wid == 0) ? 0 : warp_sums[wid - 1];
        int excl = carry + excl_warp + incl - v;
        if (i < NN) { g_rowstart[i] = excl; g_cursor[i] = excl; }
        int blocktotal = warp_sums[31];
        carry += blocktotal;
        __syncthreads();
    }
    if (threadIdx.x == 0) g_rowstart[NN] = carry;
}

// scatter edge src ids into CSR buckets (by dst)
__global__ void k_scatter(const int* __restrict__ ei) {
    int e = blockIdx.x * blockDim.x + threadIdx.x;
    if (e < NE) {
        int d = ei[NE + e];
        int p = atomicAdd(&g_cursor[d], 1);
        g_csrc[p] = ei[e];
    }
}

// embedding lookup: h[i] = emb[x[i]]
__global__ void k_embed(const int* __restrict__ x, const float* __restrict__ emb) {
    int i = blockIdx.x * blockDim.x + threadIdx.x;
    if (i < NN) {
        int lab = x[i];
        g_h[i * 3 + 0] = emb[lab * 3 + 0];
        g_h[i * 3 + 1] = emb[lab * 3 + 1];
        g_h[i * 3 + 2] = emb[lab * 3 + 2];
    }
}

// 3-dim aggregation: warp per node, edge-parallel lanes + warp reduce
__global__ void k_gather3() {
    int wid = threadIdx.x >> 5, lane = threadIdx.x & 31;
    int node = blockIdx.x * 8 + wid;
    if (node >= NN) return;
    int rs = g_rowstart[node], re = g_rowstart[node + 1];
    float a0 = 0.f, a1 = 0.f, a2 = 0.f;
    for (int e = rs + lane; e < re; e += 32) {
        int s = g_csrc[e];
        a0 += g_h[s * 3 + 0];
        a1 += g_h[s * 3 + 1];
        a2 += g_h[s * 3 + 2];
    }
    #pragma unroll
    for (int d = 16; d > 0; d >>= 1) {
        a0 += __shfl_down_sync(0xFFFFFFFFu, a0, d);
        a1 += __shfl_down_sync(0xFFFFFFFFu, a1, d);
        a2 += __shfl_down_sync(0xFFFFFFFFu, a2, d);
    }
    if (lane == 0) {
        g_aggr1[node * 3 + 0] = a0;
        g_aggr1[node * 3 + 1] = a1;
        g_aggr1[node * 3 + 2] = a2;
    }
}

// conv1 dense (3 -> 64): h1 = leaky(aggr1 @ w_rel + h @ w_root + b); also tf32 image
__global__ void k_conv1(const float* __restrict__ w_rel, const float* __restrict__ w_root,
                        const float* __restrict__ b) {
    __shared__ float swr[192], swo[192], sb[64];
    for (int i = threadIdx.x; i < 192; i += 256) { swr[i] = w_rel[i]; swo[i] = w_root[i]; }
    if (threadIdx.x < 64) sb[threadIdx.x] = b[threadIdx.x];
    __syncthreads();
    int node = blockIdx.x * 4 + (threadIdx.x >> 6);
    int j = threadIdx.x & 63;
    if (node >= NN) return;
    float a0 = g_aggr1[node * 3 + 0], a1 = g_aggr1[node * 3 + 1], a2 = g_aggr1[node * 3 + 2];
    float h0 = g_h[node * 3 + 0], h1v = g_h[node * 3 + 1], h2 = g_h[node * 3 + 2];
    float o = sb[j];
    o += a0 * swr[0 * 64 + j] + a1 * swr[1 * 64 + j] + a2 * swr[2 * 64 + j];
    o += h0 * swo[0 * 64 + j] + h1v * swo[1 * 64 + j] + h2 * swo[2 * 64 + j];
    float r = lrelu(o);
    g_h1[node * 64 + j] = r;
    g_h1T[node * 64 + j] = f2tf32(r);
}

// 64-dim aggregation: warp per node, 2 floats/lane; writes tf32 image directly
__global__ void k_gather64(const float* __restrict__ X, uint32_t* __restrict__ outT) {
    int wid = threadIdx.x >> 5, lane = threadIdx.x & 31;
    int node = blockIdx.x * 8 + wid;
    if (node >= NN) return;
    int rs = g_rowstart[node], re = g_rowstart[node + 1];
    const float2* X2 = (const float2*)X;
    float2 acc = make_float2(0.f, 0.f);
    for (int e = rs; e < re; ++e) {
        int s = g_csrc[e];
        float2 v = X2[s * 32 + lane];
        acc.x += v.x; acc.y += v.y;
    }
    uint2 t;
    t.x = f2tf32(acc.x); t.y = f2tf32(acc.y);
    ((uint2*)outT)[node * 32 + lane] = t;
}

// 256-dim aggregation with configurable strides (in floats).
// outF/outT may each be null.
__global__ void k_gather256(const float* __restrict__ X, int xs,
                            const float* __restrict__ addend, int as,
                            float* __restrict__ outF, uint32_t* __restrict__ outT,
                            int fuse_leaky) {
    int wid = threadIdx.x >> 5, lane = threadIdx.x & 31;
    int node = blockIdx.x * 8 + wid;
    if (node >= NN) return;
    int rs = g_rowstart[node], re = g_rowstart[node + 1];
    const float4* X4 = (const float4*)X;
    int xs4 = xs >> 2;
    float4 a0 = make_float4(0.f, 0.f, 0.f, 0.f);
    float4 a1 = make_float4(0.f, 0.f, 0.f, 0.f);
    for (int e = rs; e < re; ++e) {
        int s = g_csrc[e];
        float4 v0 = X4[(size_t)s * xs4 + lane * 2];
        float4 v1 = X4[(size_t)s * xs4 + lane * 2 + 1];
        a0.x += v0.x; a0.y += v0.y; a0.z += v0.z; a0.w += v0.w;
        a1.x += v1.x; a1.y += v1.y; a1.z += v1.z; a1.w += v1.w;
    }
    if (fuse_leaky) {
        const float4* A4 = (const float4*)addend;
        size_t ai = (size_t)node * (as >> 2) + lane * 2;
        float4 p0 = A4[ai], p1 = A4[ai + 1];
        a0.x = lrelu(a0.x + p0.x); a0.y = lrelu(a0.y + p0.y);
        a0.z = lrelu(a0.z + p0.z); a0.w = lrelu(a0.w + p0.w);
        a1.x = lrelu(a1.x + p1.x); a1.y = lrelu(a1.y + p1.y);
        a1.z = lrelu(a1.z + p1.z); a1.w = lrelu(a1.w + p1.w);
    }
    size_t o = (size_t)node * 64 + lane * 2;
    if (outF) {
        ((float4*)outF)[o] = a0;
        ((float4*)outF)[o + 1] = a1;
    }
    if (outT) {
        uint4 t0, t1;
        t0.x = f2tf32(a0.x); t0.y = f2tf32(a0.y); t0.z = f2tf32(a0.z); t0.w = f2tf32(a0.w);
        t1.x = f2tf32(a1.x); t1.y = f2tf32(a1.y); t1.z = f2tf32(a1.z); t1.w = f2tf32(a1.w);
        ((uint4*)outT)[o] = t0;
        ((uint4*)outT)[o + 1] = t1;
    }
}

// ---- weight prep: transpose to [N, Ktot] row-major + tf32-convert ----
__global__ void k_prep(const float* __restrict__ w2_rel, const float* __restrict__ w2_root,
                       const float* __restrict__ we_rel, const float* __restrict__ we_root,
                       const float* __restrict__ wd_rel, const float* __restrict__ wd_root,
                       const float* __restrict__ be) {
    int idx = blockIdx.x * blockDim.x + threadIdx.x;
    if (idx < 131072) {                       // Wt2: [1024][128]
        int n = idx >> 7, k = idx & 127;
        g_Wt2[idx] = f2tf32((k < 64) ? w2_rel[k * 1024 + n] : w2_root[(k - 64) * 1024 + n]);
    } else if (idx < 131072 + 524288) {       // WtE: [512][1024]
        int j = idx - 131072;
        int n = j >> 10, k = j & 1023;
        g_WtE[j] = f2tf32((n < 256) ? we_rel[k * 256 + n] : we_root[k * 256 + (n - 256)]);
    } else if (idx < 131072 + 1048576) {      // WtD: [1024][512]
        int j = idx - 655360;
        int n = j >> 9, k = j & 511;
        g_WtD[j] = f2tf32((k < 256) ? wd_rel[k * 1024 + n] : wd_root[(k - 256) * 1024 + n]);
    } else if (idx < 131072 + 1048576 + 512) { // bcat
        int j = idx - 1179648;
        g_bcat[j] = (j < 256) ? 0.f : be[j - 256];
    }
}

// ---------------- TF32 mma.sync GEMM: BM=128, BN=256, BK=16, 4-stage cp.async ----------------
// C = act( [A1|A2] @ Bt^T + bias ). A* tf32-preconverted [M,K] row-major,
// Bt [N,Ktot] tf32 row-major. 256 threads = 8 warps (2x4), warp tile 64x64.
// Smem rows padded to 20 words (conflict-free LDS, 16B-aligned cp.async).
// Requires: K1,K2 multiples of 16; N multiple of 256; Ktot/16 >= STAGES-1.
#define STAGES 4
#define SLOT_A (128 * 20)
#define SLOT_B (256 * 20)
#define SLOT_ST (SLOT_A + SLOT_B)

__global__ __launch_bounds__(256, 1) void gemm_mt(
    const uint32_t* __restrict__ A1, const uint32_t* __restrict__ A2, int K1, int K2,
    const uint32_t* __restrict__ Bt, const float* __restrict__ bias,
    float* __restrict__ C, uint32_t* __restrict__ CT,
    int M, int N, int leaky)
{
    extern __shared__ uint32_t sm[];   // [STAGES][SLOT_ST]

    const int tid = threadIdx.x;
    const int m0 = blockIdx.y * 128, n0 = blockIdx.x * 256;
    const int warp = tid >> 5, lane = tid & 31;
    const int wm = (warp >> 2) * 64, wn = (warp & 3) * 64;
    const int group = lane >> 2, tig = lane & 3;

    const int Ktot = K1 + K2;
    const int nkt = Ktot >> 4;

    // producer chunk mapping (16B chunks): A has 512, B has 1024
    const int car0 = tid >> 2, caj = (tid & 3) * 4;        // A chunks tid, tid+256
    const int car1 = (tid + 256) >> 2;

    float acc[4][8][4];
    #pragma unroll
    for (int i = 0; i < 4; i++)
        #pragma unroll
        for (int j = 0; j < 8; j++)
            #pragma unroll
            for (int q = 0; q < 4; q++) acc[i][j][q] = 0.f;

    auto issue = [&](int kt, int st) {
        const int k0 = kt << 4;
        const uint32_t* A; int Ks, kk;
        if (k0 < K1) { A = A1; Ks = K1; kk = k0; }
        else         { A = A2; Ks = K2; kk = k0 - K1; }
        uint32_t* baseA = sm + st * SLOT_ST;
        uint32_t* baseB = baseA + SLOT_A;
        // A: 2 chunks per thread
        {
            int gm = m0 + car0;
            cp_async16(smem_u32(baseA + car0 * 20 + caj),
                       A + (size_t)gm * Ks + kk + caj, (gm < M) ? 16 : 0);
            gm = m0 + car1;
            cp_async16(smem_u32(baseA + car1 * 20 + caj),
                       A + (size_t)gm * Ks + kk + caj, (gm < M) ? 16 : 0);
        }
        // B: 4 chunks per thread (rows always in-bounds: N multiple of 256)
        #pragma unroll
        for (int c = 0; c < 4; ++c) {
            int row = (tid + c * 256) >> 2;
            cp_async16(smem_u32(baseB + row * 20 + caj),
                       Bt + (size_t)(n0 + row) * Ktot + k0 + caj, 16);
        }
        cp_commit();
    };

    #pragma unroll
    for (int p = 0; p < STAGES - 1; ++p) issue(p, p);

    for (int kt = 0; kt < nkt; ++kt) {
        cp_wait2();
        __syncthreads();

        if (kt + STAGES - 1 < nkt) issue(kt + STAGES - 1, (kt + STAGES - 1) % STAGES);
        else cp_commit();

        const uint32_t* As = sm + (kt % STAGES) * SLOT_ST;
        const uint32_t* Bs = As + SLOT_A;

        #pragma unroll
        for (int ks = 0; ks < 16; ks += 8) {
            uint32_t af[4][4], bf[8][2];
            #pragma unroll
            for (int mt = 0; mt < 4; mt++) {
                int m = wm + mt * 16 + group;
                af[mt][0] = As[m * 20 + ks + tig];
                af[mt][1] = As[(m + 8) * 20 + ks + tig];
                af[mt][2] = As[m * 20 + ks + tig + 4];
                af[mt][3] = As[(m + 8) * 20 + ks + tig + 4];
            }
            #pragma unroll
            for (int nt = 0; nt < 8; nt++) {
                int n = wn + nt * 8 + group;
                bf[nt][0] = Bs[n * 20 + ks + tig];
                bf[nt][1] = Bs[n * 20 + ks + tig + 4];
            }
            #pragma unroll
            for (int mt = 0; mt < 4; mt++)
                #pragma unroll
                for (int nt = 0; nt < 8; nt++)
                    mma_tf32(acc[mt][nt], af[mt], bf[nt]);
        }
    }

    // epilogue
    #pragma unroll
    for (int nt = 0; nt < 8; nt++) {
        int col = n0 + wn + nt * 8 + tig * 2;
        float bv0 = bias ? bias[col] : 0.f;
        float bv1 = bias ? bias[col + 1] : 0.f;
        #pragma unroll
        for (int mt = 0; mt < 4; mt++) {
            int row0 = m0 + wm + mt * 16 + group;
            int row1 = row0 + 8;
            float v0 = acc[mt][nt][0] + bv0, v1 = acc[mt][nt][1] + bv1;
            float v2 = acc[mt][nt][2] + bv0, v3 = acc[mt][nt][3] + bv1;
            if (leaky) { v0 = lrelu(v0); v1 = lrelu(v1); v2 = lrelu(v2); v3 = lrelu(v3); }
            if (row0 < M) {
                *(float2*)(C + (size_t)row0 * N + col) = make_float2(v0, v1);
                if (CT) {
                    uint2 t; t.x = f2tf32(v0); t.y = f2tf32(v1);
                    *(uint2*)(CT + (size_t)row0 * N + col) = t;
                }
            }
            if (row1 < M) {
                *(float2*)(C + (size_t)row1 * N + col) = make_float2(v2, v3);
                if (CT) {
                    uint2 t; t.x = f2tf32(v2); t.y = f2tf32(v3);
                    *(uint2*)(CT + (size_t)row1 * N + col) = t;
                }
            }
        }
    }
}

// ---------------- pooling (batch is sorted -> segmented sum) + logits ----------------
__global__ void k_bounds(const int* __restrict__ batch) {
    int i = blockIdx.x * blockDim.x + threadIdx.x;
    if (i < NN) {
        int b = batch[i];
        int prev = (i == 0) ? -1 : batch[i - 1];
        for (int g = prev + 1; g <= b; g++) g_gstart[g] = i;
        if (i == NN - 1)
            for (int g = b + 1; g <= NG; g++) g_gstart[g] = NN;
    }
}
__global__ void k_pool2() {
    int g = blockIdx.x, c = threadIdx.x;   // 256 threads = 256 channels
    int s = g_gstart[g], e = g_gstart[g + 1];
    float acc = 0.f;
    for (int i = s; i < e; i++) acc += g_latent[(size_t)i * 256 + c];
    g_pooled[g * 256 + c] = acc;
    if (c == 0) g_counts[g] = (float)(e - s);
}
__global__ void k_logits(const float* __restrict__ w_lin, const float* __restrict__ b_lin,
                         float* __restrict__ out) {
    int idx = blockIdx.x * blockDim.x + threadIdx.x;
    if (idx >= NG * 7) return;
    int g = idx / 7, o = idx % 7;
    float cnt = g_counts[g];
    float inv = 1.0f / fmaxf(cnt, 1.0f);
    float s = 0.f;
    for (int c = 0; c < 256; c++)
        s += g_pooled[g * 256 + c] * w_lin[c * 7 + o];
    out[idx] = s * inv + b_lin[o];
}

// ---------------- launch ----------------
extern "C" void kernel_launch(void* const* d_in, const int* in_sizes, int n_in,
                              void* d_out, int out_size) {
    const int*   x       = (const int*)d_in[0];
    const int*   ei      = (const int*)d_in[1];
    const int*   batch   = (const int*)d_in[2];
    const float* emb     = (const float*)d_in[3];
    const float* w1_rel  = (const float*)d_in[4];
    const float* w1_root = (const float*)d_in[5];
    const float* b1      = (const float*)d_in[6];
    const float* w2_rel  = (const float*)d_in[7];
    const float* w2_root = (const float*)d_in[8];
    const float* b2      = (const float*)d_in[9];
    const float* we_rel  = (const float*)d_in[10];
    const float* we_root = (const float*)d_in[11];
    const float* be      = (const float*)d_in[12];
    const float* wd_rel  = (const float*)d_in[13];
    const float* wd_root = (const float*)d_in[14];
    const float* bd      = (const float*)d_in[15];
    const float* w_lin   = (const float*)d_in[16];
    const float* b_lin   = (const float*)d_in[17];

    float* out = (float*)d_out;
    float* out_logits = out;                              // [256*7]
    float* out_rec    = out + 1792;                       // [50000*1024]
    float* out_orig   = out + 1792 + (size_t)NN * 1024;   // [50000*1024]

    // resolve scratch symbol addresses
    void *p_deg, *p_h1, *p_h1T, *p_aggr2T, *p_origT, *p_enc, *p_latent, *p_latentT,
         *p_aggrLT, *p_Wt2, *p_WtE, *p_WtD, *p_bcat;
    cudaGetSymbolAddress(&p_deg, g_deg);
    cudaGetSymbolAddress(&p_h1, g_h1);
    cudaGetSymbolAddress(&p_h1T, g_h1T);
    cudaGetSymbolAddress(&p_aggr2T, g_aggr2T);
    cudaGetSymbolAddress(&p_origT, g_origT);
    cudaGetSymbolAddress(&p_enc, g_enc);
    cudaGetSymbolAddress(&p_latent, g_latent);
    cudaGetSymbolAddress(&p_latentT, g_latentT);
    cudaGetSymbolAddress(&p_aggrLT, g_aggrLT);
    cudaGetSymbolAddress(&p_Wt2, g_Wt2);
    cudaGetSymbolAddress(&p_WtE, g_WtE);
    cudaGetSymbolAddress(&p_WtD, g_WtD);
    cudaGetSymbolAddress(&p_bcat, g_bcat);

    const int GEMM_SMEM = STAGES * SLOT_ST * 4;   // 122880 bytes
    static int attr_set = 0;
    if (!attr_set) {
        cudaFuncSetAttribute(gemm_mt, cudaFuncAttributeMaxDynamicSharedMemorySize, GEMM_SMEM);
        attr_set = 1;
    }
    const int MB = (NN + 127) / 128;

    // ---- CSR build (by dst) ----
    k_zero_int<<<(NN + 255) / 256, 256>>>((int*)p_deg, NN);
    k_hist<<<(NE + 255) / 256, 256>>>(ei);
    k_scan<<<1, 1024>>>();
    k_scatter<<<(NE + 255) / 256, 256>>>(ei);

    // ---- weight prep (transpose + tf32) ----
    k_prep<<<(131072 + 1048576 + 512 + 255) / 256, 256>>>(
        w2_rel, w2_root, we_rel, we_root, wd_rel, wd_root, be);

    // ---- layer 1 ----
    k_embed<<<(NN + 255) / 256, 256>>>(x, emb);
    k_gather3<<<(NN + 7) / 8, 256>>>();
    k_conv1<<<(NN + 3) / 4, 256>>>(w1_rel, w1_root, b1);

    // ---- layer 2 (conv2): original = leaky([aggr(h1)|h1] @ Wt2^T + b2), + tf32 image ----
    k_gather64<<<(NN + 7) / 8, 256>>>((const float*)p_h1, (uint32_t*)p_aggr2T);
    gemm_mt<<<dim3(4, MB), 256, GEMM_SMEM>>>(
        (const uint32_t*)p_aggr2T, (const uint32_t*)p_h1T, 64, 64,
        (const uint32_t*)p_Wt2, b2, out_orig, (uint32_t*)p_origT, NN, 1024, 1);

    // ---- encoder: fused single GEMM N=512 -> [Yrel | lpre] ----
    gemm_mt<<<dim3(2, MB), 256, GEMM_SMEM>>>(
        (const uint32_t*)p_origT, nullptr, 1024, 0,
        (const uint32_t*)p_WtE, (const float*)p_bcat, (float*)p_enc, nullptr, NN, 512, 0);
    // latent = leaky(aggr(enc[:, :256]) + enc[:, 256:]); f32 + tf32 images
    k_gather256<<<(NN + 7) / 8, 256>>>((const float*)p_enc, 512,
                                       (const float*)p_enc + 256, 512,
                                       (float*)p_latent, (uint32_t*)p_latentT, 1);

    // ---- pooling + logits (segmented; batch is sorted) ----
    k_bounds<<<(NN + 255) / 256, 256>>>(batch);
    k_pool2<<<NG, 256>>>();
    k_logits<<<(NG * 7 + 255) / 256, 256>>>(w_lin, b_lin, out_logits);

    // ---- decoder: reconstructed = leaky([aggr(latent)|latent] @ WtD^T + bd) ----
    k_gather256<<<(NN + 7) / 8, 256>>>((const float*)p_latent, 256, nullptr, 0,
                                       nullptr, (uint32_t*)p_aggrLT, 0);
    gemm_mt<<<dim3(4, MB), 256, GEMM_SMEM>>>(
        (const uint32_t*)p_aggrLT, (const uint32_t*)p_latentT, 256, 256,
        (const uint32_t*)p_WtD, bd, out_rec, nullptr, NN, 1024, 1);

    (void)in_sizes; (void)n_in; (void)out_size;
}

// round 15
// speedup vs baseline: 1.0920x; 1.0920x over previous
#include <cuda_runtime.h>
#include <cuda_bf16.h>
#include <stdint.h>

// Problem constants (fixed by the dataset)
#define NN 50000
#define NE 800000
#define NG 256
// dims: emb 3 -> 64 -> 1024 -> 256 -> (1024, 7)

// ---------------- static scratch (no allocation allowed) ----------------
__device__ float    g_h[NN * 3];
__device__ float    g_aggr1[NN * 3];
__device__ float    g_h1[NN * 64];
__device__ uint32_t g_h1T[NN * 64];            // tf32 image of h1
__device__ uint32_t g_aggr2T[NN * 64];         // tf32 image of aggr(h1)
__device__ uint32_t g_origT[(size_t)NN * 1024];// tf32 image of original
__device__ float    g_enc[(size_t)NN * 512];   // fused [Yrel | lpre] (f32)
__device__ float    g_latent[NN * 256];
__device__ uint32_t g_latentT[NN * 256];       // tf32 image of latent
__device__ uint32_t g_aggrLT[NN * 256];        // tf32 image of aggr(latent)
__device__ uint32_t g_Wt2[1024 * 128];         // [n][k] tf32: k<64 rel | k>=64 root
__device__ uint32_t g_WtE[512 * 1024];         // [n][k] tf32: n<256 rel | n>=256 root
__device__ uint32_t g_WtD[1024 * 512];         // [n][k] tf32: k<256 rel | k>=256 root
__device__ float    g_bcat[512];               // [0 | be]
__device__ float    g_pooled[NG * 256];
__device__ float    g_counts[NG];
__device__ int      g_gstart[NG + 1];
__device__ int      g_deg[NN];
__device__ int      g_rowstart[NN + 1];
__device__ int      g_cursor[NN];
__device__ int      g_csrc[NE];

__device__ __forceinline__ float lrelu(float v) { return v >= 0.f ? v : 0.01f * v; }

__device__ __forceinline__ uint32_t f2tf32(float f) {
    uint32_t r;
    asm("cvt.rna.tf32.f32 %0, %1;" : "=r"(r) : "f"(f));
    return r;
}

__device__ __forceinline__ void mma_tf32(float c[4], const uint32_t a[4], const uint32_t b[2]) {
    asm volatile(
        "mma.sync.aligned.m16n8k8.row.col.f32.tf32.tf32.f32 "
        "{%0,%1,%2,%3}, {%4,%5,%6,%7}, {%8,%9}, {%0,%1,%2,%3};"
        : "+f"(c[0]), "+f"(c[1]), "+f"(c[2]), "+f"(c[3])
        : "r"(a[0]), "r"(a[1]), "r"(a[2]), "r"(a[3]), "r"(b[0]), "r"(b[1]));
}

__device__ __forceinline__ uint32_t smem_u32(const void* p) {
    return (uint32_t)__cvta_generic_to_shared(p);
}
__device__ __forceinline__ void cp_async16(uint32_t dst, const void* src, int src_bytes) {
    asm volatile("cp.async.cg.shared.global [%0], [%1], 16, %2;"
                 :: "r"(dst), "l"(src), "r"(src_bytes));
}
__device__ __forceinline__ void cp_commit() {
    asm volatile("cp.async.commit_group;");
}
__device__ __forceinline__ void cp_wait3() {
    asm volatile("cp.async.wait_group 3;");
}

// ---------------- tiny utility kernels ----------------
__global__ void k_zero_int(int* p, int n) {
    int i = blockIdx.x * blockDim.x + threadIdx.x;
    if (i < n) p[i] = 0;
}

// histogram of dst
__global__ void k_hist(const int* __restrict__ ei) {
    int e = blockIdx.x * blockDim.x + threadIdx.x;
    if (e < NE) atomicAdd(&g_deg[ei[NE + e]], 1);
}

// single-block exclusive scan over g_deg -> g_rowstart, g_cursor
__global__ void k_scan() {
    __shared__ int warp_sums[32];
    int lane = threadIdx.x & 31, wid = threadIdx.x >> 5;
    int carry = 0;
    for (int base = 0; base < NN; base += 1024) {
        int i = base + threadIdx.x;
        int v = (i < NN) ? g_deg[i] : 0;
        int incl = v;
        #pragma unroll
        for (int d = 1; d < 32; d <<= 1) {
            int t = __shfl_up_sync(0xFFFFFFFFu, incl, d);
            if (lane >= d) incl += t;
        }
        if (lane == 31) warp_sums[wid] = incl;
        __syncthreads();
        if (wid == 0) {
            int s = warp_sums[lane];
            #pragma unroll
            for (int d = 1; d < 32; d <<= 1) {
                int t = __shfl_up_sync(0xFFFFFFFFu, s, d);
                if (lane >= d) s += t;
            }
            warp_sums[lane] = s;
        }
        __syncthreads();
        int excl_warp = (wid == 0) ? 0 : warp_sums[wid - 1];
        int excl = carry + excl_warp + incl - v;
        if (i < NN) { g_rowstart[i] = excl; g_cursor[i] = excl; }
        int blocktotal = warp_sums[31];
        carry += blocktotal;
        __syncthreads();
    }
    if (threadIdx.x == 0) g_rowstart[NN] = carry;
}

// scatter edge src ids into CSR buckets (by dst)
__global__ void k_scatter(const int* __restrict__ ei) {
    int e = blockIdx.x * blockDim.x + threadIdx.x;
    if (e < NE) {
        int d = ei[NE + e];
        int p = atomicAdd(&g_cursor[d], 1);
        g_csrc[p] = ei[e];
    }
}

// embedding lookup: h[i] = emb[x[i]]
__global__ void k_embed(const int* __restrict__ x, const float* __restrict__ emb) {
    int i = blockIdx.x * blockDim.x + threadIdx.x;
    if (i < NN) {
        int lab = x[i];
        g_h[i * 3 + 0] = emb[lab * 3 + 0];
        g_h[i * 3 + 1] = emb[lab * 3 + 1];
        g_h[i * 3 + 2] = emb[lab * 3 + 2];
    }
}

// 3-dim aggregation: warp per node, edge-parallel lanes + warp reduce
__global__ void k_gather3() {
    int wid = threadIdx.x >> 5, lane = threadIdx.x & 31;
    int node = blockIdx.x * 8 + wid;
    if (node >= NN) return;
    int rs = g_rowstart[node], re = g_rowstart[node + 1];
    float a0 = 0.f, a1 = 0.f, a2 = 0.f;
    for (int e = rs + lane; e < re; e += 32) {
        int s = g_csrc[e];
        a0 += g_h[s * 3 + 0];
        a1 += g_h[s * 3 + 1];
        a2 += g_h[s * 3 + 2];
    }
    #pragma unroll
    for (int d = 16; d > 0; d >>= 1) {
        a0 += __shfl_down_sync(0xFFFFFFFFu, a0, d);
        a1 += __shfl_down_sync(0xFFFFFFFFu, a1, d);
        a2 += __shfl_down_sync(0xFFFFFFFFu, a2, d);
    }
    if (lane == 0) {
        g_aggr1[node * 3 + 0] = a0;
        g_aggr1[node * 3 + 1] = a1;
        g_aggr1[node * 3 + 2] = a2;
    }
}

// conv1 dense (3 -> 64): h1 = leaky(aggr1 @ w_rel + h @ w_root + b); also tf32 image
__global__ void k_conv1(const float* __restrict__ w_rel, const float* __restrict__ w_root,
                        const float* __restrict__ b) {
    __shared__ float swr[192], swo[192], sb[64];
    for (int i = threadIdx.x; i < 192; i += 256) { swr[i] = w_rel[i]; swo[i] = w_root[i]; }
    if (threadIdx.x < 64) sb[threadIdx.x] = b[threadIdx.x];
    __syncthreads();
    int node = blockIdx.x * 4 + (threadIdx.x >> 6);
    int j = threadIdx.x & 63;
    if (node >= NN) return;
    float a0 = g_aggr1[node * 3 + 0], a1 = g_aggr1[node * 3 + 1], a2 = g_aggr1[node * 3 + 2];
    float h0 = g_h[node * 3 + 0], h1v = g_h[node * 3 + 1], h2 = g_h[node * 3 + 2];
    float o = sb[j];
    o += a0 * swr[0 * 64 + j] + a1 * swr[1 * 64 + j] + a2 * swr[2 * 64 + j];
    o += h0 * swo[0 * 64 + j] + h1v * swo[1 * 64 + j] + h2 * swo[2 * 64 + j];
    float r = lrelu(o);
    g_h1[node * 64 + j] = r;
    g_h1T[node * 64 + j] = f2tf32(r);
}

// 64-dim aggregation: warp per node, 2 floats/lane; 2x edge unroll; tf32 image out
__global__ void k_gather64(const float* __restrict__ X, uint32_t* __restrict__ outT) {
    int wid = threadIdx.x >> 5, lane = threadIdx.x & 31;
    int node = blockIdx.x * 8 + wid;
    if (node >= NN) return;
    int rs = g_rowstart[node], re = g_rowstart[node + 1];
    const float2* X2 = (const float2*)X;
    float2 acc = make_float2(0.f, 0.f);
    int e = rs;
    for (; e + 1 < re; e += 2) {
        int s0 = g_csrc[e], s1 = g_csrc[e + 1];
        float2 v0 = X2[s0 * 32 + lane];
        float2 v1 = X2[s1 * 32 + lane];
        acc.x += v0.x; acc.y += v0.y;
        acc.x += v1.x; acc.y += v1.y;
    }
    if (e < re) {
        int s = g_csrc[e];
        float2 v = X2[s * 32 + lane];
        acc.x += v.x; acc.y += v.y;
    }
    uint2 t;
    t.x = f2tf32(acc.x); t.y = f2tf32(acc.y);
    ((uint2*)outT)[node * 32 + lane] = t;
}

// 256-dim aggregation with configurable strides (in floats); 2x edge unroll.
// outF/outT may each be null.
__global__ void k_gather256(const float* __restrict__ X, int xs,
                            const float* __restrict__ addend, int as,
                            float* __restrict__ outF, uint32_t* __restrict__ outT,
                            int fuse_leaky) {
    int wid = threadIdx.x >> 5, lane = threadIdx.x & 31;
    int node = blockIdx.x * 8 + wid;
    if (node >= NN) return;
    int rs = g_rowstart[node], re = g_rowstart[node + 1];
    const float4* X4 = (const float4*)X;
    int xs4 = xs >> 2;
    float4 a0 = make_float4(0.f, 0.f, 0.f, 0.f);
    float4 a1 = make_float4(0.f, 0.f, 0.f, 0.f);
    int e = rs;
    for (; e + 1 < re; e += 2) {
        int s0 = g_csrc[e], s1 = g_csrc[e + 1];
        float4 u0 = X4[(size_t)s0 * xs4 + lane * 2];
        float4 u1 = X4[(size_t)s0 * xs4 + lane * 2 + 1];
        float4 w0 = X4[(size_t)s1 * xs4 + lane * 2];
        float4 w1 = X4[(size_t)s1 * xs4 + lane * 2 + 1];
        a0.x += u0.x; a0.y += u0.y; a0.z += u0.z; a0.w += u0.w;
        a1.x += u1.x; a1.y += u1.y; a1.z += u1.z; a1.w += u1.w;
        a0.x += w0.x; a0.y += w0.y; a0.z += w0.z; a0.w += w0.w;
        a1.x += w1.x; a1.y += w1.y; a1.z += w1.z; a1.w += w1.w;
    }
    if (e < re) {
        int s = g_csrc[e];
        float4 v0 = X4[(size_t)s * xs4 + lane * 2];
        float4 v1 = X4[(size_t)s * xs4 + lane * 2 + 1];
        a0.x += v0.x; a0.y += v0.y; a0.z += v0.z; a0.w += v0.w;
        a1.x += v1.x; a1.y += v1.y; a1.z += v1.z; a1.w += v1.w;
    }
    if (fuse_leaky) {
        const float4* A4 = (const float4*)addend;
        size_t ai = (size_t)node * (as >> 2) + lane * 2;
        float4 p0 = A4[ai], p1 = A4[ai + 1];
        a0.x = lrelu(a0.x + p0.x); a0.y = lrelu(a0.y + p0.y);
        a0.z = lrelu(a0.z + p0.z); a0.w = lrelu(a0.w + p0.w);
        a1.x = lrelu(a1.x + p1.x); a1.y = lrelu(a1.y + p1.y);
        a1.z = lrelu(a1.z + p1.z); a1.w = lrelu(a1.w + p1.w);
    }
    size_t o = (size_t)node * 64 + lane * 2;
    if (outF) {
        ((float4*)outF)[o] = a0;
        ((float4*)outF)[o + 1] = a1;
    }
    if (outT) {
        uint4 t0, t1;
        t0.x = f2tf32(a0.x); t0.y = f2tf32(a0.y); t0.z = f2tf32(a0.z); t0.w = f2tf32(a0.w);
        t1.x = f2tf32(a1.x); t1.y = f2tf32(a1.y); t1.z = f2tf32(a1.z); t1.w = f2tf32(a1.w);
        ((uint4*)outT)[o] = t0;
        ((uint4*)outT)[o + 1] = t1;
    }
}

// ---- weight prep: transpose to [N, Ktot] row-major + tf32-convert ----
__global__ void k_prep(const float* __restrict__ w2_rel, const float* __restrict__ w2_root,
                       const float* __restrict__ we_rel, const float* __restrict__ we_root,
                       const float* __restrict__ wd_rel, const float* __restrict__ wd_root,
                       const float* __restrict__ be) {
    int idx = blockIdx.x * blockDim.x + threadIdx.x;
    if (idx < 131072) {                       // Wt2: [1024][128]
        int n = idx >> 7, k = idx & 127;
        g_Wt2[idx] = f2tf32((k < 64) ? w2_rel[k * 1024 + n] : w2_root[(k - 64) * 1024 + n]);
    } else if (idx < 131072 + 524288) {       // WtE: [512][1024]
        int j = idx - 131072;
        int n = j >> 10, k = j & 1023;
        g_WtE[j] = f2tf32((n < 256) ? we_rel[k * 256 + n] : we_root[k * 256 + (n - 256)]);
    } else if (idx < 131072 + 1048576) {      // WtD: [1024][512]
        int j = idx - 655360;
        int n = j >> 9, k = j & 511;
        g_WtD[j] = f2tf32((k < 256) ? wd_rel[k * 1024 + n] : wd_root[(k - 256) * 1024 + n]);
    } else if (idx < 131072 + 1048576 + 512) { // bcat
        int j = idx - 1179648;
        g_bcat[j] = (j < 256) ? 0.f : be[j - 256];
    }
}

// ---------------- TF32 mma.sync GEMM, 5-stage cp.async pipeline ----------------
// C = act( [A1|A2] @ Bt^T + bias ). A* are tf32-preconverted [M,K] row-major,
// Bt is [N,Ktot] tf32 row-major. BM=BN=128, BK=16, STAGES=5, 256 threads (8 warps,
// warp tile 64x32), 2 CTAs/SM. Smem rows padded to 20 words: conflict-free
// fragment LDS, 16B-aligned cp.async. Requires K1,K2 multiples of 16, nkt >= 4.
#define STAGES 5
#define SLOT  (128 * 20)          // words per operand per stage

__global__ __launch_bounds__(256, 2) void gemm_mt(
    const uint32_t* __restrict__ A1, const uint32_t* __restrict__ A2, int K1, int K2,
    const uint32_t* __restrict__ Bt, const float* __restrict__ bias,
    float* __restrict__ C, uint32_t* __restrict__ CT,
    int M, int N, int leaky)
{
    extern __shared__ uint32_t sm[];   // [STAGES][2*SLOT]

    const int tid = threadIdx.x;
    const int m0 = blockIdx.y * 128, n0 = blockIdx.x * 128;
    const int warp = tid >> 5, lane = tid & 31;
    const int wm = (warp >> 2) * 64, wn = (warp & 3) * 32;
    const int group = lane >> 2, tig = lane & 3;

    const int Ktot = K1 + K2;
    const int nkt = Ktot >> 4;

    // producer chunk mapping: chunks c = tid and tid+256 (512 chunks of 16B per operand)
    const int cm0 = tid >> 2, cj0 = (tid & 3) * 4;
    const int cm1 = (tid + 256) >> 2, cj1 = cj0;

    float acc[4][4][4];
    #pragma unroll
    for (int i = 0; i < 4; i++)
        #pragma unroll
        for (int j = 0; j < 4; j++)
            #pragma unroll
            for (int q = 0; q < 4; q++) acc[i][j][q] = 0.f;

    auto issue = [&](int kt, int st) {
        const int k0 = kt << 4;
        const uint32_t* A; int Ks, kk;
        if (k0 < K1) { A = A1; Ks = K1; kk = k0; }
        else         { A = A2; Ks = K2; kk = k0 - K1; }
        uint32_t* baseA = sm + st * 2 * SLOT;
        uint32_t* baseB = baseA + SLOT;
        {
            int gm = m0 + cm0;
            cp_async16(smem_u32(baseA + cm0 * 20 + cj0),
                       A + (size_t)gm * Ks + kk + cj0, (gm < M) ? 16 : 0);
            gm = m0 + cm1;
            cp_async16(smem_u32(baseA + cm1 * 20 + cj1),
                       A + (size_t)gm * Ks + kk + cj1, (gm < M) ? 16 : 0);
        }
        {
            cp_async16(smem_u32(baseB + cm0 * 20 + cj0),
                       Bt + (size_t)(n0 + cm0) * Ktot + k0 + cj0, 16);
            cp_async16(smem_u32(baseB + cm1 * 20 + cj1),
                       Bt + (size_t)(n0 + cm1) * Ktot + k0 + cj1, 16);
        }
        cp_commit();
    };

    // prologue: tiles 0..STAGES-2 (nkt >= 8 for all uses)
    #pragma unroll
    for (int p = 0; p < STAGES - 1; ++p) issue(p, p);

    for (int kt = 0; kt < nkt; ++kt) {
        cp_wait3();            // tile kt's group complete (<= STAGES-2 pending)
        __syncthreads();       // cross-thread visibility; stage (kt-1)%S fully consumed

        if (kt + STAGES - 1 < nkt) issue(kt + STAGES - 1, (kt + STAGES - 1) % STAGES);
        else cp_commit();      // keep group count consistent

        const uint32_t* As = sm + (kt % STAGES) * 2 * SLOT;
        const uint32_t* Bs = As + SLOT;

        #pragma unroll
        for (int ks = 0; ks < 16; ks += 8) {
            uint32_t af[4][4], bf[4][2];
            #pragma unroll
            for (int mt = 0; mt < 4; mt++) {
                int m = wm + mt * 16 + group;
                af[mt][0] = As[m * 20 + ks + tig];
                af[mt][1] = As[(m + 8) * 20 + ks + tig];
                af[mt][2] = As[m * 20 + ks + tig + 4];
                af[mt][3] = As[(m + 8) * 20 + ks + tig + 4];
            }
            #pragma unroll
            for (int nt = 0; nt < 4; nt++) {
                int n = wn + nt * 8 + group;
                bf[nt][0] = Bs[n * 20 + ks + tig];
                bf[nt][1] = Bs[n * 20 + ks + tig + 4];
            }
            #pragma unroll
            for (int mt = 0; mt < 4; mt++)
                #pragma unroll
                for (int nt = 0; nt < 4; nt++)
                    mma_tf32(acc[mt][nt], af[mt], bf[nt]);
        }
    }

    // epilogue
    #pragma unroll
    for (int nt = 0; nt < 4; nt++) {
        int col = n0 + wn + nt * 8 + tig * 2;
        float bv0 = bias ? bias[col] : 0.f;
        float bv1 = bias ? bias[col + 1] : 0.f;
        #pragma unroll
        for (int mt = 0; mt < 4; mt++) {
            int row0 = m0 + wm + mt * 16 + group;
            int row1 = row0 + 8;
            float v0 = acc[mt][nt][0] + bv0, v1 = acc[mt][nt][1] + bv1;
            float v2 = acc[mt][nt][2] + bv0, v3 = acc[mt][nt][3] + bv1;
            if (leaky) { v0 = lrelu(v0); v1 = lrelu(v1); v2 = lrelu(v2); v3 = lrelu(v3); }
            if (row0 < M) {
                *(float2*)(C + (size_t)row0 * N + col) = make_float2(v0, v1);
                if (CT) {
                    uint2 t; t.x = f2tf32(v0); t.y = f2tf32(v1);
                    *(uint2*)(CT + (size_t)row0 * N + col) = t;
                }
            }
            if (row1 < M) {
                *(float2*)(C + (size_t)row1 * N + col) = make_float2(v2, v3);
                if (CT) {
                    uint2 t; t.x = f2tf32(v2); t.y = f2tf32(v3);
                    *(uint2*)(CT + (size_t)row1 * N + col) = t;
                }
            }
        }
    }
}

// ---------------- pooling (batch is sorted -> segmented sum) + logits ----------------
__global__ void k_bounds(const int* __restrict__ batch) {
    int i = blockIdx.x * blockDim.x + threadIdx.x;
    if (i < NN) {
        int b = batch[i];
        int prev = (i == 0) ? -1 : batch[i - 1];
        for (int g = prev + 1; g <= b; g++) g_gstart[g] = i;
        if (i == NN - 1)
            for (int g = b + 1; g <= NG; g++) g_gstart[g] = NN;
    }
}
__global__ void k_pool2() {
    int g = blockIdx.x, c = threadIdx.x;   // 256 threads = 256 channels
    int s = g_gstart[g], e = g_gstart[g + 1];
    float acc = 0.f;
    for (int i = s; i < e; i++) acc += g_latent[(size_t)i * 256 + c];
    g_pooled[g * 256 + c] = acc;
    if (c == 0) g_counts[g] = (float)(e - s);
}
__global__ void k_logits(const float* __restrict__ w_lin, const float* __restrict__ b_lin,
                         float* __restrict__ out) {
    int idx = blockIdx.x * blockDim.x + threadIdx.x;
    if (idx >= NG * 7) return;
    int g = idx / 7, o = idx % 7;
    float cnt = g_counts[g];
    float inv = 1.0f / fmaxf(cnt, 1.0f);
    float s = 0.f;
    for (int c = 0; c < 256; c++)
        s += g_pooled[g * 256 + c] * w_lin[c * 7 + o];
    out[idx] = s * inv + b_lin[o];
}

// ---------------- launch ----------------
extern "C" void kernel_launch(void* const* d_in, const int* in_sizes, int n_in,
                              void* d_out, int out_size) {
    const int*   x       = (const int*)d_in[0];
    const int*   ei      = (const int*)d_in[1];
    const int*   batch   = (const int*)d_in[2];
    const float* emb     = (const float*)d_in[3];
    const float* w1_rel  = (const float*)d_in[4];
    const float* w1_root = (const float*)d_in[5];
    const float* b1      = (const float*)d_in[6];
    const float* w2_rel  = (const float*)d_in[7];
    const float* w2_root = (const float*)d_in[8];
    const float* b2      = (const float*)d_in[9];
    const float* we_rel  = (const float*)d_in[10];
    const float* we_root = (const float*)d_in[11];
    const float* be      = (const float*)d_in[12];
    const float* wd_rel  = (const float*)d_in[13];
    const float* wd_root = (const float*)d_in[14];
    const float* bd      = (const float*)d_in[15];
    const float* w_lin   = (const float*)d_in[16];
    const float* b_lin   = (const float*)d_in[17];

    float* out = (float*)d_out;
    float* out_logits = out;                              // [256*7]
    float* out_rec    = out + 1792;                       // [50000*1024]
    float* out_orig   = out + 1792 + (size_t)NN * 1024;   // [50000*1024]

    // resolve scratch symbol addresses
    void *p_deg, *p_h1, *p_h1T, *p_aggr2T, *p_origT, *p_enc, *p_latent, *p_latentT,
         *p_aggrLT, *p_Wt2, *p_WtE, *p_WtD, *p_bcat;
    cudaGetSymbolAddress(&p_deg, g_deg);
    cudaGetSymbolAddress(&p_h1, g_h1);
    cudaGetSymbolAddress(&p_h1T, g_h1T);
    cudaGetSymbolAddress(&p_aggr2T, g_aggr2T);
    cudaGetSymbolAddress(&p_origT, g_origT);
    cudaGetSymbolAddress(&p_enc, g_enc);
    cudaGetSymbolAddress(&p_latent, g_latent);
    cudaGetSymbolAddress(&p_latentT, g_latentT);
    cudaGetSymbolAddress(&p_aggrLT, g_aggrLT);
    cudaGetSymbolAddress(&p_Wt2, g_Wt2);
    cudaGetSymbolAddress(&p_WtE, g_WtE);
    cudaGetSymbolAddress(&p_WtD, g_WtD);
    cudaGetSymbolAddress(&p_bcat, g_bcat);

    const int GEMM_SMEM = STAGES * 2 * SLOT * 4;   // 102400 bytes (2 CTAs/SM: 200KB)
    static int attr_set = 0;
    if (!attr_set) {
        cudaFuncSetAttribute(gemm_mt, cudaFuncAttributeMaxDynamicSharedMemorySize, GEMM_SMEM);
        attr_set = 1;
    }
    const int MB = (NN + 127) / 128;

    // ---- CSR build (by dst) ----
    k_zero_int<<<(NN + 255) / 256, 256>>>((int*)p_deg, NN);
    k_hist<<<(NE + 255) / 256, 256>>>(ei);
    k_scan<<<1, 1024>>>();
    k_scatter<<<(NE + 255) / 256, 256>>>(ei);

    // ---- weight prep (transpose + tf32) ----
    k_prep<<<(131072 + 1048576 + 512 + 255) / 256, 256>>>(
        w2_rel, w2_root, we_rel, we_root, wd_rel, wd_root, be);

    // ---- layer 1 ----
    k_embed<<<(NN + 255) / 256, 256>>>(x, emb);
    k_gather3<<<(NN + 7) / 8, 256>>>();
    k_conv1<<<(NN + 3) / 4, 256>>>(w1_rel, w1_root, b1);

    // ---- layer 2 (conv2): original = leaky([aggr(h1)|h1] @ Wt2^T + b2), + tf32 image ----
    k_gather64<<<(NN + 7) / 8, 256>>>((const float*)p_h1, (uint32_t*)p_aggr2T);
    gemm_mt<<<dim3(8, MB), 256, GEMM_SMEM>>>(
        (const uint32_t*)p_aggr2T, (const uint32_t*)p_h1T, 64, 64,
        (const uint32_t*)p_Wt2, b2, out_orig, (uint32_t*)p_origT, NN, 1024, 1);

    // ---- encoder: fused single GEMM N=512 -> [Yrel | lpre] ----
    gemm_mt<<<dim3(4, MB), 256, GEMM_SMEM>>>(
        (const uint32_t*)p_origT, nullptr, 1024, 0,
        (const uint32_t*)p_WtE, (const float*)p_bcat, (float*)p_enc, nullptr, NN, 512, 0);
    // latent = leaky(aggr(enc[:, :256]) + enc[:, 256:]); f32 + tf32 images
    k_gather256<<<(NN + 7) / 8, 256>>>((const float*)p_enc, 512,
                                       (const float*)p_enc + 256, 512,
                                       (float*)p_latent, (uint32_t*)p_latentT, 1);

    // ---- pooling + logits (segmented; batch is sorted) ----
    k_bounds<<<(NN + 255) / 256, 256>>>(batch);
    k_pool2<<<NG, 256>>>();
    k_logits<<<(NG * 7 + 255) / 256, 256>>>(w_lin, b_lin, out_logits);

    // ---- decoder: reconstructed = leaky([aggr(latent)|latent] @ WtD^T + bd) ----
    k_gather256<<<(NN + 7) / 8, 256>>>((const float*)p_latent, 256, nullptr, 0,
                                       nullptr, (uint32_t*)p_aggrLT, 0);
    gemm_mt<<<dim3(8, MB), 256, GEMM_SMEM>>>(
        (const uint32_t*)p_aggrLT, (const uint32_t*)p_latentT, 256, 256,
        (const uint32_t*)p_WtD, bd, out_rec, nullptr, NN, 1024, 1);

    (void)in_sizes; (void)n_in; (void)out_size;
}

// round 16
// speedup vs baseline: 1.1435x; 1.0472x over previous
#include <cuda_runtime.h>
#include <cuda_bf16.h>
#include <stdint.h>

// Problem constants (fixed by the dataset)
#define NN 50000
#define NE 800000
#define NG 256
// dims: emb 3 -> 64 -> 1024 -> 256 -> (1024, 7)

// ---------------- static scratch (no allocation allowed) ----------------
__device__ float    g_h1[NN * 64];
__device__ uint32_t g_h1T[NN * 64];            // tf32 image of h1
__device__ uint32_t g_aggr2T[NN * 64];         // tf32 image of aggr(h1)
__device__ uint32_t g_origT[(size_t)NN * 1024];// tf32 image of original
__device__ float    g_enc[(size_t)NN * 512];   // fused [Yrel | lpre] (f32)
__device__ float    g_latent[NN * 256];
__device__ uint32_t g_latentT[NN * 256];       // tf32 image of latent
__device__ uint32_t g_aggrLT[NN * 256];        // tf32 image of aggr(latent)
__device__ uint32_t g_Wt2[1024 * 128];         // [n][k] tf32: k<64 rel | k>=64 root
__device__ uint32_t g_WtE[512 * 1024];         // [n][k] tf32: n<256 rel | n>=256 root
__device__ uint32_t g_WtD[1024 * 512];         // [n][k] tf32: k<256 rel | k>=256 root
__device__ float    g_bcat[512];               // [0 | be]
__device__ float    g_pooled[NG * 256];
__device__ float    g_counts[NG];
__device__ int      g_gstart[NG + 1];
__device__ int      g_deg[NN];
__device__ int      g_rowstart[NN + 1];
__device__ int      g_cursor[NN];
__device__ int      g_csrc[NE];

__device__ __forceinline__ float lrelu(float v) { return v >= 0.f ? v : 0.01f * v; }

__device__ __forceinline__ uint32_t f2tf32(float f) {
    uint32_t r;
    asm("cvt.rna.tf32.f32 %0, %1;" : "=r"(r) : "f"(f));
    return r;
}

__device__ __forceinline__ void mma_tf32(float c[4], const uint32_t a[4], const uint32_t b[2]) {
    asm volatile(
        "mma.sync.aligned.m16n8k8.row.col.f32.tf32.tf32.f32 "
        "{%0,%1,%2,%3}, {%4,%5,%6,%7}, {%8,%9}, {%0,%1,%2,%3};"
        : "+f"(c[0]), "+f"(c[1]), "+f"(c[2]), "+f"(c[3])
        : "r"(a[0]), "r"(a[1]), "r"(a[2]), "r"(a[3]), "r"(b[0]), "r"(b[1]));
}

__device__ __forceinline__ uint32_t smem_u32(const void* p) {
    return (uint32_t)__cvta_generic_to_shared(p);
}
__device__ __forceinline__ void cp_async16(uint32_t dst, const void* src, int src_bytes) {
    asm volatile("cp.async.cg.shared.global [%0], [%1], 16, %2;"
                 :: "r"(dst), "l"(src), "r"(src_bytes));
}
__device__ __forceinline__ void cp_commit() {
    asm volatile("cp.async.commit_group;");
}
__device__ __forceinline__ void cp_wait3() {
    asm volatile("cp.async.wait_group 3;");
}

// ---------------- tiny utility kernels ----------------
__global__ void k_zero_int(int* p, int n) {
    int i = blockIdx.x * blockDim.x + threadIdx.x;
    if (i < n) p[i] = 0;
}

// histogram of dst
__global__ void k_hist(const int* __restrict__ ei) {
    int e = blockIdx.x * blockDim.x + threadIdx.x;
    if (e < NE) atomicAdd(&g_deg[ei[NE + e]], 1);
}

// single-block exclusive scan over g_deg -> g_rowstart, g_cursor
__global__ void k_scan() {
    __shared__ int warp_sums[32];
    int lane = threadIdx.x & 31, wid = threadIdx.x >> 5;
    int carry = 0;
    for (int base = 0; base < NN; base += 1024) {
        int i = base + threadIdx.x;
        int v = (i < NN) ? g_deg[i] : 0;
        int incl = v;
        #pragma unroll
        for (int d = 1; d < 32; d <<= 1) {
            int t = __shfl_up_sync(0xFFFFFFFFu, incl, d);
            if (lane >= d) incl += t;
        }
        if (lane == 31) warp_sums[wid] = incl;
        __syncthreads();
        if (wid == 0) {
            int s = warp_sums[lane];
            #pragma unroll
            for (int d = 1; d < 32; d <<= 1) {
                int t = __shfl_up_sync(0xFFFFFFFFu, s, d);
                if (lane >= d) s += t;
            }
            warp_sums[lane] = s;
        }
        __syncthreads();
        int excl_warp = (wid == 0) ? 0 : warp_sums[wid - 1];
        int excl = carry + excl_warp + incl - v;
        if (i < NN) { g_rowstart[i] = excl; g_cursor[i] = excl; }
        int blocktotal = warp_sums[31];
        carry += blocktotal;
        __syncthreads();
    }
    if (threadIdx.x == 0) g_rowstart[NN] = carry;
}

// scatter edge src ids into CSR buckets (by dst)
__global__ void k_scatter(const int* __restrict__ ei) {
    int e = blockIdx.x * blockDim.x + threadIdx.x;
    if (e < NE) {
        int d = ei[NE + e];
        int p = atomicAdd(&g_cursor[d], 1);
        g_csrc[p] = ei[e];
    }
}

// fused embed + 3-dim aggregation + conv1 (3 -> 64).
// Warp per node: edge-parallel lanes sum emb[x[src]] (3 dims), shfl-reduce
// (same tree as before), broadcast, then lanes compute 2 output cols each.
__global__ void k_g3conv1(const int* __restrict__ x, const float* __restrict__ emb,
                          const float* __restrict__ w_rel, const float* __restrict__ w_root,
                          const float* __restrict__ b) {
    __shared__ float semb[30];
    __shared__ float swr[192], swo[192], sb[64];
    int tid = threadIdx.x;
    if (tid < 30) semb[tid] = emb[tid];
    for (int i = tid; i < 192; i += 256) { swr[i] = w_rel[i]; swo[i] = w_root[i]; }
    if (tid < 64) sb[tid] = b[tid];
    __syncthreads();
    int wid = tid >> 5, lane = tid & 31;
    int node = blockIdx.x * 8 + wid;
    if (node >= NN) return;
    int rs = g_rowstart[node], re = g_rowstart[node + 1];
    float a0 = 0.f, a1 = 0.f, a2 = 0.f;
    for (int e = rs + lane; e < re; e += 32) {
        int lab = x[g_csrc[e]];
        a0 += semb[lab * 3 + 0];
        a1 += semb[lab * 3 + 1];
        a2 += semb[lab * 3 + 2];
    }
    #pragma unroll
    for (int d = 16; d > 0; d >>= 1) {
        a0 += __shfl_down_sync(0xFFFFFFFFu, a0, d);
        a1 += __shfl_down_sync(0xFFFFFFFFu, a1, d);
        a2 += __shfl_down_sync(0xFFFFFFFFu, a2, d);
    }
    a0 = __shfl_sync(0xFFFFFFFFu, a0, 0);
    a1 = __shfl_sync(0xFFFFFFFFu, a1, 0);
    a2 = __shfl_sync(0xFFFFFFFFu, a2, 0);
    int lab = x[node];
    float h0 = semb[lab * 3 + 0], h1v = semb[lab * 3 + 1], h2 = semb[lab * 3 + 2];
    #pragma unroll
    for (int jj = 0; jj < 2; jj++) {
        int j = lane + jj * 32;
        float o = sb[j];
        o += a0 * swr[0 * 64 + j] + a1 * swr[1 * 64 + j] + a2 * swr[2 * 64 + j];
        o += h0 * swo[0 * 64 + j] + h1v * swo[1 * 64 + j] + h2 * swo[2 * 64 + j];
        float r = lrelu(o);
        g_h1[node * 64 + j] = r;
        g_h1T[node * 64 + j] = f2tf32(r);
    }
}

// 64-dim aggregation: warp per node, 2 floats/lane; 2x edge unroll; tf32 image out
__global__ void k_gather64(const float* __restrict__ X, uint32_t* __restrict__ outT) {
    int wid = threadIdx.x >> 5, lane = threadIdx.x & 31;
    int node = blockIdx.x * 8 + wid;
    if (node >= NN) return;
    int rs = g_rowstart[node], re = g_rowstart[node + 1];
    const float2* X2 = (const float2*)X;
    float2 acc = make_float2(0.f, 0.f);
    int e = rs;
    for (; e + 1 < re; e += 2) {
        int s0 = g_csrc[e], s1 = g_csrc[e + 1];
        float2 v0 = X2[s0 * 32 + lane];
        float2 v1 = X2[s1 * 32 + lane];
        acc.x += v0.x; acc.y += v0.y;
        acc.x += v1.x; acc.y += v1.y;
    }
    if (e < re) {
        int s = g_csrc[e];
        float2 v = X2[s * 32 + lane];
        acc.x += v.x; acc.y += v.y;
    }
    uint2 t;
    t.x = f2tf32(acc.x); t.y = f2tf32(acc.y);
    ((uint2*)outT)[node * 32 + lane] = t;
}

// 256-dim aggregation with configurable strides (in floats); 2x edge unroll.
// outF/outT may each be null.
__global__ void k_gather256(const float* __restrict__ X, int xs,
                            const float* __restrict__ addend, int as,
                            float* __restrict__ outF, uint32_t* __restrict__ outT,
                            int fuse_leaky) {
    int wid = threadIdx.x >> 5, lane = threadIdx.x & 31;
    int node = blockIdx.x * 8 + wid;
    if (node >= NN) return;
    int rs = g_rowstart[node], re = g_rowstart[node + 1];
    const float4* X4 = (const float4*)X;
    int xs4 = xs >> 2;
    float4 a0 = make_float4(0.f, 0.f, 0.f, 0.f);
    float4 a1 = make_float4(0.f, 0.f, 0.f, 0.f);
    int e = rs;
    for (; e + 1 < re; e += 2) {
        int s0 = g_csrc[e], s1 = g_csrc[e + 1];
        float4 u0 = X4[(size_t)s0 * xs4 + lane * 2];
        float4 u1 = X4[(size_t)s0 * xs4 + lane * 2 + 1];
        float4 w0 = X4[(size_t)s1 * xs4 + lane * 2];
        float4 w1 = X4[(size_t)s1 * xs4 + lane * 2 + 1];
        a0.x += u0.x; a0.y += u0.y; a0.z += u0.z; a0.w += u0.w;
        a1.x += u1.x; a1.y += u1.y; a1.z += u1.z; a1.w += u1.w;
        a0.x += w0.x; a0.y += w0.y; a0.z += w0.z; a0.w += w0.w;
        a1.x += w1.x; a1.y += w1.y; a1.z += w1.z; a1.w += w1.w;
    }
    if (e < re) {
        int s = g_csrc[e];
        float4 v0 = X4[(size_t)s * xs4 + lane * 2];
        float4 v1 = X4[(size_t)s * xs4 + lane * 2 + 1];
        a0.x += v0.x; a0.y += v0.y; a0.z += v0.z; a0.w += v0.w;
        a1.x += v1.x; a1.y += v1.y; a1.z += v1.z; a1.w += v1.w;
    }
    if (fuse_leaky) {
        const float4* A4 = (const float4*)addend;
        size_t ai = (size_t)node * (as >> 2) + lane * 2;
        float4 p0 = A4[ai], p1 = A4[ai + 1];
        a0.x = lrelu(a0.x + p0.x); a0.y = lrelu(a0.y + p0.y);
        a0.z = lrelu(a0.z + p0.z); a0.w = lrelu(a0.w + p0.w);
        a1.x = lrelu(a1.x + p1.x); a1.y = lrelu(a1.y + p1.y);
        a1.z = lrelu(a1.z + p1.z); a1.w = lrelu(a1.w + p1.w);
    }
    size_t o = (size_t)node * 64 + lane * 2;
    if (outF) {
        ((float4*)outF)[o] = a0;
        ((float4*)outF)[o + 1] = a1;
    }
    if (outT) {
        uint4 t0, t1;
        t0.x = f2tf32(a0.x); t0.y = f2tf32(a0.y); t0.z = f2tf32(a0.z); t0.w = f2tf32(a0.w);
        t1.x = f2tf32(a1.x); t1.y = f2tf32(a1.y); t1.z = f2tf32(a1.z); t1.w = f2tf32(a1.w);
        ((uint4*)outT)[o] = t0;
        ((uint4*)outT)[o + 1] = t1;
    }
}

// ---- weight prep: transpose to [N, Ktot] row-major + tf32-convert ----
__global__ void k_prep(const float* __restrict__ w2_rel, const float* __restrict__ w2_root,
                       const float* __restrict__ we_rel, const float* __restrict__ we_root,
                       const float* __restrict__ wd_rel, const float* __restrict__ wd_root,
                       const float* __restrict__ be) {
    int idx = blockIdx.x * blockDim.x + threadIdx.x;
    if (idx < 131072) {                       // Wt2: [1024][128]
        int n = idx >> 7, k = idx & 127;
        g_Wt2[idx] = f2tf32((k < 64) ? w2_rel[k * 1024 + n] : w2_root[(k - 64) * 1024 + n]);
    } else if (idx < 131072 + 524288) {       // WtE: [512][1024]
        int j = idx - 131072;
        int n = j >> 10, k = j & 1023;
        g_WtE[j] = f2tf32((n < 256) ? we_rel[k * 256 + n] : we_root[k * 256 + (n - 256)]);
    } else if (idx < 131072 + 1048576) {      // WtD: [1024][512]
        int j = idx - 655360;
        int n = j >> 9, k = j & 511;
        g_WtD[j] = f2tf32((k < 256) ? wd_rel[k * 1024 + n] : wd_root[(k - 256) * 1024 + n]);
    } else if (idx < 131072 + 1048576 + 512) { // bcat
        int j = idx - 1179648;
        g_bcat[j] = (j < 256) ? 0.f : be[j - 256];
    }
}

// ---------------- TF32 mma.sync GEMM, 5-stage cp.async pipeline ----------------
// C = act( [A1|A2] @ Bt^T + bias ). A* are tf32-preconverted [M,K] row-major,
// Bt is [N,Ktot] tf32 row-major. BM=BN=128, BK=16, STAGES=5, 256 threads (8 warps,
// warp tile 64x32), 2 CTAs/SM. Smem rows padded to 20 words: conflict-free
// fragment LDS, 16B-aligned cp.async. Requires K1,K2 multiples of 16, nkt >= 4.
#define STAGES 5
#define SLOT  (128 * 20)          // words per operand per stage

__global__ __launch_bounds__(256, 2) void gemm_mt(
    const uint32_t* __restrict__ A1, const uint32_t* __restrict__ A2, int K1, int K2,
    const uint32_t* __restrict__ Bt, const float* __restrict__ bias,
    float* __restrict__ C, uint32_t* __restrict__ CT,
    int M, int N, int leaky)
{
    extern __shared__ uint32_t sm[];   // [STAGES][2*SLOT]

    const int tid = threadIdx.x;
    const int m0 = blockIdx.y * 128, n0 = blockIdx.x * 128;
    const int warp = tid >> 5, lane = tid & 31;
    const int wm = (warp >> 2) * 64, wn = (warp & 3) * 32;
    const int group = lane >> 2, tig = lane & 3;

    const int Ktot = K1 + K2;
    const int nkt = Ktot >> 4;

    // producer chunk mapping: chunks c = tid and tid+256 (512 chunks of 16B per operand)
    const int cm0 = tid >> 2, cj0 = (tid & 3) * 4;
    const int cm1 = (tid + 256) >> 2, cj1 = cj0;

    float acc[4][4][4];
    #pragma unroll
    for (int i = 0; i < 4; i++)
        #pragma unroll
        for (int j = 0; j < 4; j++)
            #pragma unroll
            for (int q = 0; q < 4; q++) acc[i][j][q] = 0.f;

    auto issue = [&](int kt, int st) {
        const int k0 = kt << 4;
        const uint32_t* A; int Ks, kk;
        if (k0 < K1) { A = A1; Ks = K1; kk = k0; }
        else         { A = A2; Ks = K2; kk = k0 - K1; }
        uint32_t* baseA = sm + st * 2 * SLOT;
        uint32_t* baseB = baseA + SLOT;
        {
            int gm = m0 + cm0;
            cp_async16(smem_u32(baseA + cm0 * 20 + cj0),
                       A + (size_t)gm * Ks + kk + cj0, (gm < M) ? 16 : 0);
            gm = m0 + cm1;
            cp_async16(smem_u32(baseA + cm1 * 20 + cj1),
                       A + (size_t)gm * Ks + kk + cj1, (gm < M) ? 16 : 0);
        }
        {
            cp_async16(smem_u32(baseB + cm0 * 20 + cj0),
                       Bt + (size_t)(n0 + cm0) * Ktot + k0 + cj0, 16);
            cp_async16(smem_u32(baseB + cm1 * 20 + cj1),
                       Bt + (size_t)(n0 + cm1) * Ktot + k0 + cj1, 16);
        }
        cp_commit();
    };

    // prologue: tiles 0..STAGES-2 (nkt >= 8 for all uses)
    #pragma unroll
    for (int p = 0; p < STAGES - 1; ++p) issue(p, p);

    for (int kt = 0; kt < nkt; ++kt) {
        cp_wait3();            // tile kt's group complete (<= STAGES-2 pending)
        __syncthreads();       // cross-thread visibility; stage (kt-1)%S fully consumed

        if (kt + STAGES - 1 < nkt) issue(kt + STAGES - 1, (kt + STAGES - 1) % STAGES);
        else cp_commit();      // keep group count consistent

        const uint32_t* As = sm + (kt % STAGES) * 2 * SLOT;
        const uint32_t* Bs = As + SLOT;

        #pragma unroll
        for (int ks = 0; ks < 16; ks += 8) {
            uint32_t af[4][4], bf[4][2];
            #pragma unroll
            for (int mt = 0; mt < 4; mt++) {
                int m = wm + mt * 16 + group;
                af[mt][0] = As[m * 20 + ks + tig];
                af[mt][1] = As[(m + 8) * 20 + ks + tig];
                af[mt][2] = As[m * 20 + ks + tig + 4];
                af[mt][3] = As[(m + 8) * 20 + ks + tig + 4];
            }
            #pragma unroll
            for (int nt = 0; nt < 4; nt++) {
                int n = wn + nt * 8 + group;
                bf[nt][0] = Bs[n * 20 + ks + tig];
                bf[nt][1] = Bs[n * 20 + ks + tig + 4];
            }
            #pragma unroll
            for (int mt = 0; mt < 4; mt++)
                #pragma unroll
                for (int nt = 0; nt < 4; nt++)
                    mma_tf32(acc[mt][nt], af[mt], bf[nt]);
        }
    }

    // epilogue
    #pragma unroll
    for (int nt = 0; nt < 4; nt++) {
        int col = n0 + wn + nt * 8 + tig * 2;
        float bv0 = bias ? bias[col] : 0.f;
        float bv1 = bias ? bias[col + 1] : 0.f;
        #pragma unroll
        for (int mt = 0; mt < 4; mt++) {
            int row0 = m0 + wm + mt * 16 + group;
            int row1 = row0 + 8;
            float v0 = acc[mt][nt][0] + bv0, v1 = acc[mt][nt][1] + bv1;
            float v2 = acc[mt][nt][2] + bv0, v3 = acc[mt][nt][3] + bv1;
            if (leaky) { v0 = lrelu(v0); v1 = lrelu(v1); v2 = lrelu(v2); v3 = lrelu(v3); }
            if (row0 < M) {
                *(float2*)(C + (size_t)row0 * N + col) = make_float2(v0, v1);
                if (CT) {
                    uint2 t; t.x = f2tf32(v0); t.y = f2tf32(v1);
                    *(uint2*)(CT + (size_t)row0 * N + col) = t;
                }
            }
            if (row1 < M) {
                *(float2*)(C + (size_t)row1 * N + col) = make_float2(v2, v3);
                if (CT) {
                    uint2 t; t.x = f2tf32(v2); t.y = f2tf32(v3);
                    *(uint2*)(CT + (size_t)row1 * N + col) = t;
                }
            }
        }
    }
}

// ---------------- pooling (batch is sorted -> segmented sum) + logits ----------------
__global__ void k_bounds(const int* __restrict__ batch) {
    int i = blockIdx.x * blockDim.x + threadIdx.x;
    if (i < NN) {
        int b = batch[i];
        int prev = (i == 0) ? -1 : batch[i - 1];
        for (int g = prev + 1; g <= b; g++) g_gstart[g] = i;
        if (i == NN - 1)
            for (int g = b + 1; g <= NG; g++) g_gstart[g] = NN;
    }
}
__global__ void k_pool2() {
    int g = blockIdx.x, c = threadIdx.x;   // 256 threads = 256 channels
    int s = g_gstart[g], e = g_gstart[g + 1];
    float acc = 0.f;
    for (int i = s; i < e; i++) acc += g_latent[(size_t)i * 256 + c];
    g_pooled[g * 256 + c] = acc;
    if (c == 0) g_counts[g] = (float)(e - s);
}
__global__ void k_logits(const float* __restrict__ w_lin, const float* __restrict__ b_lin,
                         float* __restrict__ out) {
    int idx = blockIdx.x * blockDim.x + threadIdx.x;
    if (idx >= NG * 7) return;
    int g = idx / 7, o = idx % 7;
    float cnt = g_counts[g];
    float inv = 1.0f / fmaxf(cnt, 1.0f);
    float s = 0.f;
    for (int c = 0; c < 256; c++)
        s += g_pooled[g * 256 + c] * w_lin[c * 7 + o];
    out[idx] = s * inv + b_lin[o];
}

// ---------------- launch ----------------
extern "C" void kernel_launch(void* const* d_in, const int* in_sizes, int n_in,
                              void* d_out, int out_size) {
    const int*   x       = (const int*)d_in[0];
    const int*   ei      = (const int*)d_in[1];
    const int*   batch   = (const int*)d_in[2];
    const float* emb     = (const float*)d_in[3];
    const float* w1_rel  = (const float*)d_in[4];
    const float* w1_root = (const float*)d_in[5];
    const float* b1      = (const float*)d_in[6];
    const float* w2_rel  = (const float*)d_in[7];
    const float* w2_root = (const float*)d_in[8];
    const float* b2      = (const float*)d_in[9];
    const float* we_rel  = (const float*)d_in[10];
    const float* we_root = (const float*)d_in[11];
    const float* be      = (const float*)d_in[12];
    const float* wd_rel  = (const float*)d_in[13];
    const float* wd_root = (const float*)d_in[14];
    const float* bd      = (const float*)d_in[15];
    const float* w_lin   = (const float*)d_in[16];
    const float* b_lin   = (const float*)d_in[17];

    float* out = (float*)d_out;
    float* out_logits = out;                              // [256*7]
    float* out_rec    = out + 1792;                       // [50000*1024]
    float* out_orig   = out + 1792 + (size_t)NN * 1024;   // [50000*1024]

    // resolve scratch symbol addresses
    void *p_deg, *p_h1, *p_h1T, *p_aggr2T, *p_origT, *p_enc, *p_latent, *p_latentT,
         *p_aggrLT, *p_Wt2, *p_WtE, *p_WtD, *p_bcat;
    cudaGetSymbolAddress(&p_deg, g_deg);
    cudaGetSymbolAddress(&p_h1, g_h1);
    cudaGetSymbolAddress(&p_h1T, g_h1T);
    cudaGetSymbolAddress(&p_aggr2T, g_aggr2T);
    cudaGetSymbolAddress(&p_origT, g_origT);
    cudaGetSymbolAddress(&p_enc, g_enc);
    cudaGetSymbolAddress(&p_latent, g_latent);
    cudaGetSymbolAddress(&p_latentT, g_latentT);
    cudaGetSymbolAddress(&p_aggrLT, g_aggrLT);
    cudaGetSymbolAddress(&p_Wt2, g_Wt2);
    cudaGetSymbolAddress(&p_WtE, g_WtE);
    cudaGetSymbolAddress(&p_WtD, g_WtD);
    cudaGetSymbolAddress(&p_bcat, g_bcat);

    const int GEMM_SMEM = STAGES * 2 * SLOT * 4;   // 102400 bytes (2 CTAs/SM: 200KB)
    static int attr_set = 0;
    if (!attr_set) {
        cudaFuncSetAttribute(gemm_mt, cudaFuncAttributeMaxDynamicSharedMemorySize, GEMM_SMEM);
        attr_set = 1;
    }
    const int MB = (NN + 127) / 128;

    // side stream + events for graph-parallel branches (created once; capture-legal)
    static cudaStream_t s2 = nullptr;
    static cudaEvent_t ev0 = nullptr, ev1 = nullptr, ev2 = nullptr, ev3 = nullptr;
    if (!s2) {
        cudaStreamCreateWithFlags(&s2, cudaStreamNonBlocking);
        cudaEventCreateWithFlags(&ev0, cudaEventDisableTiming);
        cudaEventCreateWithFlags(&ev1, cudaEventDisableTiming);
        cudaEventCreateWithFlags(&ev2, cudaEventDisableTiming);
        cudaEventCreateWithFlags(&ev3, cudaEventDisableTiming);
    }

    // ---- fork: weight prep + pool bounds run parallel to the CSR build ----
    cudaEventRecord(ev0, 0);
    cudaStreamWaitEvent(s2, ev0, 0);
    k_prep<<<(131072 + 1048576 + 512 + 255) / 256, 256, 0, s2>>>(
        w2_rel, w2_root, we_rel, we_root, wd_rel, wd_root, be);
    k_bounds<<<(NN + 255) / 256, 256, 0, s2>>>(batch);
    cudaEventRecord(ev1, s2);

    // ---- main: CSR build (by dst) ----
    k_zero_int<<<(NN + 255) / 256, 256>>>((int*)p_deg, NN);
    k_hist<<<(NE + 255) / 256, 256>>>(ei);
    k_scan<<<1, 1024>>>();
    k_scatter<<<(NE + 255) / 256, 256>>>(ei);

    // ---- layer 1 (fused embed + gather3 + conv1) ----
    k_g3conv1<<<(NN + 7) / 8, 256>>>(x, emb, w1_rel, w1_root, b1);

    // ---- layer 2 (conv2): original = leaky([aggr(h1)|h1] @ Wt2^T + b2), + tf32 image ----
    k_gather64<<<(NN + 7) / 8, 256>>>((const float*)p_h1, (uint32_t*)p_aggr2T);
    cudaStreamWaitEvent(0, ev1, 0);   // join: weights (and bounds) ready
    gemm_mt<<<dim3(8, MB), 256, GEMM_SMEM>>>(
        (const uint32_t*)p_aggr2T, (const uint32_t*)p_h1T, 64, 64,
        (const uint32_t*)p_Wt2, b2, out_orig, (uint32_t*)p_origT, NN, 1024, 1);

    // ---- encoder: fused single GEMM N=512 -> [Yrel | lpre] ----
    gemm_mt<<<dim3(4, MB), 256, GEMM_SMEM>>>(
        (const uint32_t*)p_origT, nullptr, 1024, 0,
        (const uint32_t*)p_WtE, (const float*)p_bcat, (float*)p_enc, nullptr, NN, 512, 0);
    // latent = leaky(aggr(enc[:, :256]) + enc[:, 256:]); f32 + tf32 images
    k_gather256<<<(NN + 7) / 8, 256>>>((const float*)p_enc, 512,
                                       (const float*)p_enc + 256, 512,
                                       (float*)p_latent, (uint32_t*)p_latentT, 1);

    // ---- fork: pooling + logits run parallel to decoder gather + GEMM ----
    cudaEventRecord(ev2, 0);
    cudaStreamWaitEvent(s2, ev2, 0);
    k_pool2<<<NG, 256, 0, s2>>>();
    k_logits<<<(NG * 7 + 255) / 256, 256, 0, s2>>>(w_lin, b_lin, out_logits);
    cudaEventRecord(ev3, s2);

    // ---- decoder: reconstructed = leaky([aggr(latent)|latent] @ WtD^T + bd) ----
    k_gather256<<<(NN + 7) / 8, 256>>>((const float*)p_latent, 256, nullptr, 0,
                                       nullptr, (uint32_t*)p_aggrLT, 0);
    gemm_mt<<<dim3(8, MB), 256, GEMM_SMEM>>>(
        (const uint32_t*)p_aggrLT, (const uint32_t*)p_latentT, 256, 256,
        (const uint32_t*)p_WtD, bd, out_rec, nullptr, NN, 1024, 1);

    // ---- join: pooling branch complete before returning ----
    cudaStreamWaitEvent(0, ev3, 0);

    (void)in_sizes; (void)n_in; (void)out_size;
}